// round 1
// baseline (speedup 1.0000x reference)
#include <cuda_runtime.h>
#include <cuda_bf16.h>
#include <cstdint>

#define Bb 8
#define Ff 16
#define Pp 196
#define Dd 768
#define Hh 12
#define HD 64
#define NTOK (Bb*Ff*Pp)          // 25088
#define QKVW (3*Dd)              // 2304

// ---------------- scratch (allocation-free: __device__ globals) ----------------
__device__ float g_qkv[(size_t)NTOK * QKVW];   // 231 MB
__device__ float g_attn[(size_t)NTOK * Dd];    // 77 MB
__device__ float g_y[(size_t)NTOK * Dd];       // 77 MB
__device__ float g_x1[(size_t)NTOK * Dd];      // 77 MB

// ---------------- SGEMM: C[M,N] = A[M,K] @ B[K,N] + bias[N] ----------------
// M % 128 == 0, N % 128 == 0, K % 8 == 0 (holds for all calls here)
__global__ __launch_bounds__(256) void sgemm_bias(
    const float* __restrict__ A, const float* __restrict__ B,
    const float* __restrict__ bias, float* __restrict__ C,
    int M, int N, int K)
{
    const int BM = 128, BN = 128, BK = 8, TM = 8, TN = 8;
    __shared__ float As[BK][BM];
    __shared__ float Bs[BK][BN];

    int tid = threadIdx.x;
    int bx = blockIdx.x;          // N tile
    int by = blockIdx.y;          // M tile
    int tx = tid % 16;
    int ty = tid / 16;

    const float* Ab = A + (size_t)by * BM * K;
    const float* Bt = B + (size_t)bx * BN;

    float acc[TM][TN];
#pragma unroll
    for (int i = 0; i < TM; i++)
#pragma unroll
        for (int j = 0; j < TN; j++) acc[i][j] = 0.f;

    int arow = tid >> 1;              // 0..127
    int acol = (tid & 1) * 4;         // 0 or 4
    int brow = tid >> 5;              // 0..7
    int bcol = (tid & 31) * 4;        // 0..124

    for (int k0 = 0; k0 < K; k0 += BK) {
        float4 a4 = *reinterpret_cast<const float4*>(Ab + (size_t)arow * K + k0 + acol);
        As[acol + 0][arow] = a4.x;
        As[acol + 1][arow] = a4.y;
        As[acol + 2][arow] = a4.z;
        As[acol + 3][arow] = a4.w;
        float4 b4 = *reinterpret_cast<const float4*>(Bt + (size_t)(k0 + brow) * N + bcol);
        *reinterpret_cast<float4*>(&Bs[brow][bcol]) = b4;
        __syncthreads();

#pragma unroll
        for (int kk = 0; kk < BK; kk++) {
            float4 ra0 = *reinterpret_cast<const float4*>(&As[kk][ty * TM]);
            float4 ra1 = *reinterpret_cast<const float4*>(&As[kk][ty * TM + 4]);
            float4 rb0 = *reinterpret_cast<const float4*>(&Bs[kk][tx * TN]);
            float4 rb1 = *reinterpret_cast<const float4*>(&Bs[kk][tx * TN + 4]);
            float ra[TM] = {ra0.x, ra0.y, ra0.z, ra0.w, ra1.x, ra1.y, ra1.z, ra1.w};
            float rb[TN] = {rb0.x, rb0.y, rb0.z, rb0.w, rb1.x, rb1.y, rb1.z, rb1.w};
#pragma unroll
            for (int i = 0; i < TM; i++)
#pragma unroll
                for (int j = 0; j < TN; j++)
                    acc[i][j] += ra[i] * rb[j];
        }
        __syncthreads();
    }

#pragma unroll
    for (int i = 0; i < TM; i++) {
        size_t row = (size_t)by * BM + ty * TM + i;
#pragma unroll
        for (int j = 0; j < TN; j += 4) {
            int col = bx * BN + tx * TN + j;
            float4 o;
            o.x = acc[i][j + 0] + bias[col + 0];
            o.y = acc[i][j + 1] + bias[col + 1];
            o.z = acc[i][j + 2] + bias[col + 2];
            o.w = acc[i][j + 3] + bias[col + 3];
            *reinterpret_cast<float4*>(C + row * N + col) = o;
        }
    }
}

// ---------------- generic small-seq attention ----------------
// One block per (sequence, head). K/V staged in smem; K rows padded to 65
// floats so the per-key strided reads are bank-conflict free.
__global__ __launch_bounds__(256) void attn_kernel(
    const float* __restrict__ qkv, float* __restrict__ out, int S, int temporal)
{
    extern __shared__ float sm[];
    int h = blockIdx.y;
    int seq = blockIdx.x;
    int base, stride;
    if (temporal) {
        int b = seq / Pp, p = seq % Pp;
        base = b * Ff * Pp + p;
        stride = Pp;
    } else {
        base = seq * Pp;
        stride = 1;
    }

    float* Ks = sm;                 // S * 65
    float* Vs = Ks + S * 65;        // S * 64
    float* qs = Vs + S * 64;        // 64
    float* sc = qs + 64;            // S
    float* red = sc + S;            // 2

    int tid = threadIdx.x;

    // stage K and V
    for (int idx = tid; idx < S * 64; idx += 256) {
        int s = idx >> 6, d = idx & 63;
        size_t row = (size_t)(base + s * stride) * QKVW;
        Ks[s * 65 + d] = qkv[row + Dd + h * HD + d];
        Vs[s * 64 + d] = qkv[row + 2 * Dd + h * HD + d];
    }
    __syncthreads();

    for (int q = 0; q < S; q++) {
        size_t qrow = (size_t)(base + q * stride);
        if (tid < 64) qs[tid] = qkv[qrow * QKVW + h * HD + tid];
        __syncthreads();

        if (tid < S) {
            const float* kr = Ks + tid * 65;
            float acc = 0.f;
#pragma unroll 16
            for (int d = 0; d < 64; d++) acc += qs[d] * kr[d];
            sc[tid] = acc * 0.125f;   // 1/sqrt(64)
        }
        __syncthreads();

        if (tid < 32) {
            float m = -1e30f;
            for (int j = tid; j < S; j += 32) m = fmaxf(m, sc[j]);
#pragma unroll
            for (int o = 16; o; o >>= 1) m = fmaxf(m, __shfl_xor_sync(0xffffffffu, m, o));
            red[0] = m;
        }
        __syncthreads();
        float smax = red[0];
        if (tid < S) sc[tid] = __expf(sc[tid] - smax);
        __syncthreads();
        if (tid < 32) {
            float s = 0.f;
            for (int j = tid; j < S; j += 32) s += sc[j];
#pragma unroll
            for (int o = 16; o; o >>= 1) s += __shfl_xor_sync(0xffffffffu, s, o);
            red[1] = 1.0f / s;
        }
        __syncthreads();
        float inv = red[1];

        if (tid < 64) {
            float acc = 0.f;
            for (int j = 0; j < S; j++) acc += sc[j] * Vs[j * 64 + tid];
            out[qrow * Dd + h * HD + tid] = acc * inv;
        }
        __syncthreads();   // protect sc/qs before next query
    }
}

// ---------------- fused residual + LayerNorm ----------------
__global__ __launch_bounds__(256) void add_ln_kernel(
    const float* __restrict__ x, const float* __restrict__ y,
    const float* __restrict__ g, const float* __restrict__ b,
    float* __restrict__ out)
{
    __shared__ float row_sm[Dd];
    __shared__ float ps[8], ps2[8];
    __shared__ float red[2];

    size_t row = blockIdx.x;
    const float* xr = x + row * Dd;
    const float* yr = y + row * Dd;
    int tid = threadIdx.x;
    int lane = tid & 31, wid = tid >> 5;

    float s = 0.f, s2 = 0.f;
    for (int d = tid; d < Dd; d += 256) {
        float v = xr[d] + yr[d];
        row_sm[d] = v;
        s += v;
        s2 += v * v;
    }
#pragma unroll
    for (int o = 16; o; o >>= 1) {
        s  += __shfl_xor_sync(0xffffffffu, s, o);
        s2 += __shfl_xor_sync(0xffffffffu, s2, o);
    }
    if (lane == 0) { ps[wid] = s; ps2[wid] = s2; }
    __syncthreads();
    if (tid < 8) {
        s = ps[tid]; s2 = ps2[tid];
#pragma unroll
        for (int o = 4; o; o >>= 1) {
            s  += __shfl_xor_sync(0xffu, s, o);
            s2 += __shfl_xor_sync(0xffu, s2, o);
        }
        if (tid == 0) {
            float mean = s / Dd;
            float var = s2 / Dd - mean * mean;
            red[0] = mean;
            red[1] = rsqrtf(var + 1e-5f);
        }
    }
    __syncthreads();
    float mean = red[0], rstd = red[1];
    for (int d = tid; d < Dd; d += 256)
        out[row * Dd + d] = (row_sm[d] - mean) * rstd * g[d] + b[d];
}

// ---------------- launch ----------------
extern "C" void kernel_launch(void* const* d_in, const int* in_sizes, int n_in,
                              void* d_out, int out_size)
{
    const float* x      = (const float*)d_in[0];
    const float* Wqkv_t = (const float*)d_in[1];
    const float* bqkv_t = (const float*)d_in[2];
    const float* Wo_t   = (const float*)d_in[3];
    const float* bo_t   = (const float*)d_in[4];
    const float* Wqkv_s = (const float*)d_in[5];
    const float* bqkv_s = (const float*)d_in[6];
    const float* Wo_s   = (const float*)d_in[7];
    const float* bo_s   = (const float*)d_in[8];
    const float* g1     = (const float*)d_in[9];
    const float* b1     = (const float*)d_in[10];
    const float* g2     = (const float*)d_in[11];
    const float* b2     = (const float*)d_in[12];
    float* out = (float*)d_out;

    float *qkv, *attn, *y, *x1;
    cudaGetSymbolAddress((void**)&qkv,  g_qkv);
    cudaGetSymbolAddress((void**)&attn, g_attn);
    cudaGetSymbolAddress((void**)&y,    g_y);
    cudaGetSymbolAddress((void**)&x1,   g_x1);

    // spatial attention needs 102 KB dynamic smem
    int smem_spatial = (Pp * 65 + Pp * 64 + 64 + Pp + 2) * (int)sizeof(float);
    int smem_temporal = (Ff * 65 + Ff * 64 + 64 + Ff + 2) * (int)sizeof(float);
    cudaFuncSetAttribute(attn_kernel, cudaFuncAttributeMaxDynamicSharedMemorySize, smem_spatial);

    dim3 gemm_qkv(QKVW / 128, NTOK / 128);   // (18, 196)
    dim3 gemm_out(Dd / 128, NTOK / 128);     // (6, 196)

    // 1. temporal QKV projection
    sgemm_bias<<<gemm_qkv, 256>>>(x, Wqkv_t, bqkv_t, qkv, NTOK, QKVW, Dd);
    // 2. temporal attention (S = 16, per (b,p) sequence)
    attn_kernel<<<dim3(Bb * Pp, Hh), 256, smem_temporal>>>(qkv, attn, Ff, 1);
    // 3. temporal out-projection
    sgemm_bias<<<gemm_out, 256>>>(attn, Wo_t, bo_t, y, NTOK, Dd, Dd);
    // 4. x1 = LN(x + y)
    add_ln_kernel<<<NTOK, 256>>>(x, y, g1, b1, x1);
    // 5. spatial QKV projection
    sgemm_bias<<<gemm_qkv, 256>>>(x1, Wqkv_s, bqkv_s, qkv, NTOK, QKVW, Dd);
    // 6. spatial attention (S = 196, per (b,f) sequence)
    attn_kernel<<<dim3(Bb * Ff, Hh), 256, smem_spatial>>>(qkv, attn, Pp, 0);
    // 7. spatial out-projection
    sgemm_bias<<<gemm_out, 256>>>(attn, Wo_s, bo_s, y, NTOK, Dd, Dd);
    // 8. out = LN(x1 + y)
    add_ln_kernel<<<NTOK, 256>>>(x1, y, g2, b2, out);
}

// round 3
// speedup vs baseline: 1.0440x; 1.0440x over previous
#include <cuda_runtime.h>
#include <cuda_bf16.h>
#include <cstdint>

#define Bb 8
#define Ff 16
#define Pp 196
#define Dd 768
#define Hh 12
#define HD 64
#define NTOK (Bb*Ff*Pp)          // 25088
#define QKVW (3*Dd)              // 2304
#define GK 768                   // K for all GEMMs
#define KCHUNKS (GK/32)          // 24

// ---------------- scratch (allocation-free: __device__ globals) ----------------
__device__ float g_qkv[(size_t)NTOK * QKVW];   // 231 MB
__device__ float g_attn[(size_t)NTOK * Dd];    // 77 MB
__device__ float g_y[(size_t)NTOK * Dd];       // 77 MB
__device__ float g_x1[(size_t)NTOK * Dd];      // 77 MB
__device__ float g_wt[(size_t)Dd * QKVW];      // 7 MB (transposed weight)

__device__ __forceinline__ float tf32r(float x) {   // round-to-nearest tf32
    uint32_t u;
    asm("cvt.rna.tf32.f32 %0, %1;" : "=r"(u) : "f"(x));
    return __uint_as_float(u);
}
__device__ __forceinline__ void mma_m16n8k8(float* c, const uint32_t* a, const uint32_t* b) {
    asm volatile(
        "mma.sync.aligned.m16n8k8.row.col.f32.tf32.tf32.f32 "
        "{%0,%1,%2,%3}, {%4,%5,%6,%7}, {%8,%9}, {%0,%1,%2,%3};"
        : "+f"(c[0]), "+f"(c[1]), "+f"(c[2]), "+f"(c[3])
        : "r"(a[0]), "r"(a[1]), "r"(a[2]), "r"(a[3]), "r"(b[0]), "r"(b[1]));
}

// ---------------- weight transpose: out[N,K] = in[K,N] ----------------
__global__ __launch_bounds__(256) void transpose32(
    const float* __restrict__ in, float* __restrict__ out, int K, int N)
{
    __shared__ float t[32][33];
    int n0 = blockIdx.x * 32, k0 = blockIdx.y * 32;
    int tx = threadIdx.x, ty = threadIdx.y;   // 32 x 8
#pragma unroll
    for (int j = 0; j < 32; j += 8)
        t[ty + j][tx] = in[(size_t)(k0 + ty + j) * N + n0 + tx];
    __syncthreads();
#pragma unroll
    for (int j = 0; j < 32; j += 8)
        out[(size_t)(n0 + ty + j) * K + k0 + tx] = t[tx][ty + j];
}

// ---------------- TF32 mma.sync GEMM: C[M,N] = A[M,768] @ Bt[N,768]^T + bias --
// 128x128 CTA tile, BK=32, 256 threads (8 warps, 2x4, warp tile 64x32).
// Smem rows padded to 36 floats -> conflict-free fragment loads.
#define ROWP 36
#define STAGE_F (128 * ROWP)     // floats per operand per stage (4608)
__global__ __launch_bounds__(256) void gemm_mma(
    const float* __restrict__ A, const float* __restrict__ Bt,
    const float* __restrict__ bias, float* __restrict__ C, int N)
{
    extern __shared__ float sm[];
    float* As = sm;                    // [2][128][36]
    float* Bs = sm + 2 * STAGE_F;      // [2][128][36]

    int tid = threadIdx.x;
    int wid = tid >> 5, lane = tid & 31;
    int wr = wid >> 2, wc = wid & 3;        // warp 2x4
    int lg = lane >> 2, lk = lane & 3;      // group-of-4 layout
    int bm = blockIdx.y * 128, bn = blockIdx.x * 128;

    const float* Ag = A  + (size_t)bm * GK;
    const float* Bg = Bt + (size_t)bn * GK;

    float acc[4][4][4];
#pragma unroll
    for (int i = 0; i < 4; i++)
#pragma unroll
        for (int j = 0; j < 4; j++)
#pragma unroll
            for (int k = 0; k < 4; k++) acc[i][j][k] = 0.f;

    int ldr = tid >> 3, lds4 = (tid & 7) * 4;   // 128 rows, 8 float4/row

    float4 ra[4], rb[4];
#pragma unroll
    for (int i = 0; i < 4; i++) {               // prologue LDG chunk 0
        int r = ldr + i * 32;
        ra[i] = *(const float4*)(Ag + (size_t)r * GK + lds4);
        rb[i] = *(const float4*)(Bg + (size_t)r * GK + lds4);
    }
#pragma unroll
    for (int i = 0; i < 4; i++) {               // STS stage 0
        int r = ldr + i * 32;
        float4 va = ra[i], vb = rb[i];
        va.x = tf32r(va.x); va.y = tf32r(va.y); va.z = tf32r(va.z); va.w = tf32r(va.w);
        vb.x = tf32r(vb.x); vb.y = tf32r(vb.y); vb.z = tf32r(vb.z); vb.w = tf32r(vb.w);
        *(float4*)(As + r * ROWP + lds4) = va;
        *(float4*)(Bs + r * ROWP + lds4) = vb;
    }
    __syncthreads();

    for (int it = 0; it < KCHUNKS; it++) {
        if (it + 1 < KCHUNKS) {
            int kc = (it + 1) * 32;
#pragma unroll
            for (int i = 0; i < 4; i++) {
                int r = ldr + i * 32;
                ra[i] = *(const float4*)(Ag + (size_t)r * GK + kc + lds4);
                rb[i] = *(const float4*)(Bg + (size_t)r * GK + kc + lds4);
            }
        }
        const uint32_t* Au = (const uint32_t*)(As + (it & 1) * STAGE_F);
        const uint32_t* Bu = (const uint32_t*)(Bs + (it & 1) * STAGE_F);
#pragma unroll
        for (int ks = 0; ks < 4; ks++) {
            int k0 = ks * 8;
            uint32_t af[4][4], bf[4][2];
#pragma unroll
            for (int mt = 0; mt < 4; mt++) {
                int r = wr * 64 + mt * 16 + lg;
                int c = k0 + lk;
                af[mt][0] = Au[r * ROWP + c];
                af[mt][1] = Au[(r + 8) * ROWP + c];
                af[mt][2] = Au[r * ROWP + c + 4];
                af[mt][3] = Au[(r + 8) * ROWP + c + 4];
            }
#pragma unroll
            for (int nt = 0; nt < 4; nt++) {
                int n = wc * 32 + nt * 8 + lg;
                int k = k0 + lk;
                bf[nt][0] = Bu[n * ROWP + k];
                bf[nt][1] = Bu[n * ROWP + k + 4];
            }
#pragma unroll
            for (int mt = 0; mt < 4; mt++)
#pragma unroll
                for (int nt = 0; nt < 4; nt++)
                    mma_m16n8k8(acc[mt][nt], af[mt], bf[nt]);
        }
        if (it + 1 < KCHUNKS) {
            int st = (it + 1) & 1;
#pragma unroll
            for (int i = 0; i < 4; i++) {
                int r = ldr + i * 32;
                float4 va = ra[i], vb = rb[i];
                va.x = tf32r(va.x); va.y = tf32r(va.y); va.z = tf32r(va.z); va.w = tf32r(va.w);
                vb.x = tf32r(vb.x); vb.y = tf32r(vb.y); vb.z = tf32r(vb.z); vb.w = tf32r(vb.w);
                *(float4*)(As + st * STAGE_F + r * ROWP + lds4) = va;
                *(float4*)(Bs + st * STAGE_F + r * ROWP + lds4) = vb;
            }
            __syncthreads();
        }
    }

    // epilogue: direct stores, float2 per (mt,nt) row pair
#pragma unroll
    for (int mt = 0; mt < 4; mt++) {
        size_t r0 = (size_t)(bm + wr * 64 + mt * 16 + lg);
#pragma unroll
        for (int nt = 0; nt < 4; nt++) {
            int c0 = bn + wc * 32 + nt * 8 + lk * 2;
            float bx = bias[c0], by = bias[c0 + 1];
            float2 v0 = make_float2(acc[mt][nt][0] + bx, acc[mt][nt][1] + by);
            float2 v1 = make_float2(acc[mt][nt][2] + bx, acc[mt][nt][3] + by);
            *(float2*)(C + r0 * N + c0) = v0;
            *(float2*)(C + (r0 + 8) * N + c0) = v1;
        }
    }
}

// ---------------- generic small-seq attention ----------------
__global__ __launch_bounds__(256) void attn_kernel(
    const float* __restrict__ qkv, float* __restrict__ out, int S, int temporal)
{
    extern __shared__ float sm[];
    int h = blockIdx.y;
    int seq = blockIdx.x;
    int base, stride;
    if (temporal) {
        int b = seq / Pp, p = seq % Pp;
        base = b * Ff * Pp + p;
        stride = Pp;
    } else {
        base = seq * Pp;
        stride = 1;
    }

    float* Ks = sm;                 // S * 65
    float* Vs = Ks + S * 65;        // S * 64
    float* qs = Vs + S * 64;        // 64
    float* sc = qs + 64;            // S
    float* red = sc + S;            // 2

    int tid = threadIdx.x;

    for (int idx = tid; idx < S * 64; idx += 256) {
        int s = idx >> 6, d = idx & 63;
        size_t row = (size_t)(base + s * stride) * QKVW;
        Ks[s * 65 + d] = qkv[row + Dd + h * HD + d];
        Vs[s * 64 + d] = qkv[row + 2 * Dd + h * HD + d];
    }
    __syncthreads();

    for (int q = 0; q < S; q++) {
        size_t qrow = (size_t)(base + q * stride);
        if (tid < 64) qs[tid] = qkv[qrow * QKVW + h * HD + tid];
        __syncthreads();

        if (tid < S) {
            const float* kr = Ks + tid * 65;
            float acc = 0.f;
#pragma unroll 16
            for (int d = 0; d < 64; d++) acc += qs[d] * kr[d];
            sc[tid] = acc * 0.125f;
        }
        __syncthreads();

        if (tid < 32) {
            float m = -1e30f;
            for (int j = tid; j < S; j += 32) m = fmaxf(m, sc[j]);
#pragma unroll
            for (int o = 16; o; o >>= 1) m = fmaxf(m, __shfl_xor_sync(0xffffffffu, m, o));
            red[0] = m;
        }
        __syncthreads();
        float smax = red[0];
        if (tid < S) sc[tid] = __expf(sc[tid] - smax);
        __syncthreads();
        if (tid < 32) {
            float s = 0.f;
            for (int j = tid; j < S; j += 32) s += sc[j];
#pragma unroll
            for (int o = 16; o; o >>= 1) s += __shfl_xor_sync(0xffffffffu, s, o);
            red[1] = 1.0f / s;
        }
        __syncthreads();
        float inv = red[1];

        if (tid < 64) {
            float acc = 0.f;
            for (int j = 0; j < S; j++) acc += sc[j] * Vs[j * 64 + tid];
            out[qrow * Dd + h * HD + tid] = acc * inv;
        }
        __syncthreads();
    }
}

// ---------------- fused residual + LayerNorm ----------------
__global__ __launch_bounds__(256) void add_ln_kernel(
    const float* __restrict__ x, const float* __restrict__ y,
    const float* __restrict__ g, const float* __restrict__ b,
    float* __restrict__ out)
{
    __shared__ float row_sm[Dd];
    __shared__ float ps[8], ps2[8];
    __shared__ float red[2];

    size_t row = blockIdx.x;
    const float* xr = x + row * Dd;
    const float* yr = y + row * Dd;
    int tid = threadIdx.x;
    int lane = tid & 31, wid = tid >> 5;

    float s = 0.f, s2 = 0.f;
    for (int d = tid; d < Dd; d += 256) {
        float v = xr[d] + yr[d];
        row_sm[d] = v;
        s += v;
        s2 += v * v;
    }
#pragma unroll
    for (int o = 16; o; o >>= 1) {
        s  += __shfl_xor_sync(0xffffffffu, s, o);
        s2 += __shfl_xor_sync(0xffffffffu, s2, o);
    }
    if (lane == 0) { ps[wid] = s; ps2[wid] = s2; }
    __syncthreads();
    if (tid < 8) {
        s = ps[tid]; s2 = ps2[tid];
#pragma unroll
        for (int o = 4; o; o >>= 1) {
            s  += __shfl_xor_sync(0xffu, s, o);
            s2 += __shfl_xor_sync(0xffu, s2, o);
        }
        if (tid == 0) {
            float mean = s / Dd;
            float var = s2 / Dd - mean * mean;
            red[0] = mean;
            red[1] = rsqrtf(var + 1e-5f);
        }
    }
    __syncthreads();
    float mean = red[0], rstd = red[1];
    for (int d = tid; d < Dd; d += 256)
        out[row * Dd + d] = (row_sm[d] - mean) * rstd * g[d] + b[d];
}

// ---------------- launch ----------------
extern "C" void kernel_launch(void* const* d_in, const int* in_sizes, int n_in,
                              void* d_out, int out_size)
{
    const float* x      = (const float*)d_in[0];
    const float* Wqkv_t = (const float*)d_in[1];
    const float* bqkv_t = (const float*)d_in[2];
    const float* Wo_t   = (const float*)d_in[3];
    const float* bo_t   = (const float*)d_in[4];
    const float* Wqkv_s = (const float*)d_in[5];
    const float* bqkv_s = (const float*)d_in[6];
    const float* Wo_s   = (const float*)d_in[7];
    const float* bo_s   = (const float*)d_in[8];
    const float* g1     = (const float*)d_in[9];
    const float* b1     = (const float*)d_in[10];
    const float* g2     = (const float*)d_in[11];
    const float* b2     = (const float*)d_in[12];
    float* out = (float*)d_out;

    float *qkv, *attn, *y, *x1, *wt;
    cudaGetSymbolAddress((void**)&qkv,  g_qkv);
    cudaGetSymbolAddress((void**)&attn, g_attn);
    cudaGetSymbolAddress((void**)&y,    g_y);
    cudaGetSymbolAddress((void**)&x1,   g_x1);
    cudaGetSymbolAddress((void**)&wt,   g_wt);

    int smem_spatial  = (Pp * 65 + Pp * 64 + 64 + Pp + 2) * (int)sizeof(float);
    int smem_temporal = (Ff * 65 + Ff * 64 + 64 + Ff + 2) * (int)sizeof(float);
    cudaFuncSetAttribute(attn_kernel, cudaFuncAttributeMaxDynamicSharedMemorySize, smem_spatial);

    const int GEMM_SMEM = 4 * STAGE_F * (int)sizeof(float);   // 73728 B
    cudaFuncSetAttribute(gemm_mma, cudaFuncAttributeMaxDynamicSharedMemorySize, GEMM_SMEM);

    dim3 tb(32, 8);
    dim3 tg_qkv(QKVW / 32, GK / 32);   // (72, 24)
    dim3 tg_out(Dd / 32, GK / 32);     // (24, 24)
    dim3 gg_qkv(QKVW / 128, NTOK / 128);  // (18, 196)
    dim3 gg_out(Dd / 128, NTOK / 128);    // (6, 196)

    // temporal QKV projection
    transpose32<<<tg_qkv, tb>>>(Wqkv_t, wt, GK, QKVW);
    gemm_mma<<<gg_qkv, 256, GEMM_SMEM>>>(x, wt, bqkv_t, qkv, QKVW);
    // temporal attention (S=16)
    attn_kernel<<<dim3(Bb * Pp, Hh), 256, smem_temporal>>>(qkv, attn, Ff, 1);
    // temporal out-projection
    transpose32<<<tg_out, tb>>>(Wo_t, wt, GK, Dd);
    gemm_mma<<<gg_out, 256, GEMM_SMEM>>>(attn, wt, bo_t, y, Dd);
    // x1 = LN(x + y)
    add_ln_kernel<<<NTOK, 256>>>(x, y, g1, b1, x1);
    // spatial QKV projection
    transpose32<<<tg_qkv, tb>>>(Wqkv_s, wt, GK, QKVW);
    gemm_mma<<<gg_qkv, 256, GEMM_SMEM>>>(x1, wt, bqkv_s, qkv, QKVW);
    // spatial attention (S=196)
    attn_kernel<<<dim3(Bb * Ff, Hh), 256, smem_spatial>>>(qkv, attn, Pp, 0);
    // spatial out-projection
    transpose32<<<tg_out, tb>>>(Wo_s, wt, GK, Dd);
    gemm_mma<<<gg_out, 256, GEMM_SMEM>>>(attn, wt, bo_s, y, Dd);
    // out = LN(x1 + y)
    add_ln_kernel<<<NTOK, 256>>>(x1, y, g2, b2, out);
}

// round 4
// speedup vs baseline: 1.3973x; 1.3384x over previous
#include <cuda_runtime.h>
#include <cuda_bf16.h>
#include <cstdint>

#define Bb 8
#define Ff 16
#define Pp 196
#define Dd 768
#define Hh 12
#define HD 64
#define NTOK (Bb*Ff*Pp)          // 25088
#define QKVW (3*Dd)              // 2304
#define GK 768                   // K for all GEMMs
#define KCHUNKS (GK/32)          // 24

// ---------------- scratch (allocation-free: __device__ globals) ----------------
__device__ float g_qkv[(size_t)NTOK * QKVW];   // 231 MB
__device__ float g_attn[(size_t)NTOK * Dd];    // 77 MB
__device__ float g_y[(size_t)NTOK * Dd];       // 77 MB
__device__ float g_x1[(size_t)NTOK * Dd];      // 77 MB
__device__ float g_wt[(size_t)Dd * QKVW];      // 7 MB (transposed weight)

__device__ __forceinline__ uint32_t pack_bf16(float lo, float hi) {
    __nv_bfloat162 p = __float22bfloat162_rn(make_float2(lo, hi));
    return *reinterpret_cast<uint32_t*>(&p);
}
__device__ __forceinline__ void mma_bf16(float* c, const uint32_t* a, const uint32_t* b) {
    asm volatile(
        "mma.sync.aligned.m16n8k16.row.col.f32.bf16.bf16.f32 "
        "{%0,%1,%2,%3}, {%4,%5,%6,%7}, {%8,%9}, {%0,%1,%2,%3};"
        : "+f"(c[0]), "+f"(c[1]), "+f"(c[2]), "+f"(c[3])
        : "r"(a[0]), "r"(a[1]), "r"(a[2]), "r"(a[3]), "r"(b[0]), "r"(b[1]));
}

// ---------------- weight transpose: out[N,K] = in[K,N] ----------------
__global__ __launch_bounds__(256) void transpose32(
    const float* __restrict__ in, float* __restrict__ out, int K, int N)
{
    __shared__ float t[32][33];
    int n0 = blockIdx.x * 32, k0 = blockIdx.y * 32;
    int tx = threadIdx.x, ty = threadIdx.y;   // 32 x 8
#pragma unroll
    for (int j = 0; j < 32; j += 8)
        t[ty + j][tx] = in[(size_t)(k0 + ty + j) * N + n0 + tx];
    __syncthreads();
#pragma unroll
    for (int j = 0; j < 32; j += 8)
        out[(size_t)(n0 + ty + j) * K + k0 + tx] = t[tx][ty + j];
}

// ---------------- BF16 mma.sync GEMM: C[M,N] = A[M,768] @ Bt[N,768]^T + bias --
// 128x128 CTA tile, BK=32 (bf16), 256 threads (8 warps 2x4, warp tile 64x32).
// Smem rows: 16 u32 (bf16x2) padded to 20 -> conflict-free fragment loads.
#define ROWP32 20
#define STAGE_U (128 * ROWP32)       // u32 per operand per stage (2560)
__global__ __launch_bounds__(256) void gemm_mma(
    const float* __restrict__ A, const float* __restrict__ Bt,
    const float* __restrict__ bias, float* __restrict__ C, int N)
{
    __shared__ uint32_t As[2][STAGE_U];
    __shared__ uint32_t Bs[2][STAGE_U];

    int tid = threadIdx.x;
    int wid = tid >> 5, lane = tid & 31;
    int wr = wid >> 2, wc = wid & 3;        // warp 2x4
    int lg = lane >> 2, lk = lane & 3;      // group-of-4 layout
    int bm = blockIdx.y * 128, bn = blockIdx.x * 128;

    const float* Ag = A  + (size_t)bm * GK;
    const float* Bg = Bt + (size_t)bn * GK;

    float acc[4][4][4];
#pragma unroll
    for (int i = 0; i < 4; i++)
#pragma unroll
        for (int j = 0; j < 4; j++)
#pragma unroll
            for (int k = 0; k < 4; k++) acc[i][j][k] = 0.f;

    int ldr = tid >> 1;                 // row 0..127
    int half = tid & 1;                 // which 16-float half of the 32-chunk
    int cbase = half * 16;              // f32 col offset
    int c2base = half * 8;              // u32 (bf16x2) col offset

    float4 ra[4], rb[4];
#pragma unroll
    for (int j = 0; j < 4; j++) {       // prologue LDG chunk 0
        ra[j] = *(const float4*)(Ag + (size_t)ldr * GK + cbase + j * 4);
        rb[j] = *(const float4*)(Bg + (size_t)ldr * GK + cbase + j * 4);
    }
    {
        uint4 ua0 = make_uint4(pack_bf16(ra[0].x, ra[0].y), pack_bf16(ra[0].z, ra[0].w),
                               pack_bf16(ra[1].x, ra[1].y), pack_bf16(ra[1].z, ra[1].w));
        uint4 ua1 = make_uint4(pack_bf16(ra[2].x, ra[2].y), pack_bf16(ra[2].z, ra[2].w),
                               pack_bf16(ra[3].x, ra[3].y), pack_bf16(ra[3].z, ra[3].w));
        uint4 ub0 = make_uint4(pack_bf16(rb[0].x, rb[0].y), pack_bf16(rb[0].z, rb[0].w),
                               pack_bf16(rb[1].x, rb[1].y), pack_bf16(rb[1].z, rb[1].w));
        uint4 ub1 = make_uint4(pack_bf16(rb[2].x, rb[2].y), pack_bf16(rb[2].z, rb[2].w),
                               pack_bf16(rb[3].x, rb[3].y), pack_bf16(rb[3].z, rb[3].w));
        *(uint4*)(&As[0][ldr * ROWP32 + c2base])     = ua0;
        *(uint4*)(&As[0][ldr * ROWP32 + c2base + 4]) = ua1;
        *(uint4*)(&Bs[0][ldr * ROWP32 + c2base])     = ub0;
        *(uint4*)(&Bs[0][ldr * ROWP32 + c2base + 4]) = ub1;
    }
    __syncthreads();

    for (int it = 0; it < KCHUNKS; it++) {
        if (it + 1 < KCHUNKS) {
            int kc = (it + 1) * 32;
#pragma unroll
            for (int j = 0; j < 4; j++) {
                ra[j] = *(const float4*)(Ag + (size_t)ldr * GK + kc + cbase + j * 4);
                rb[j] = *(const float4*)(Bg + (size_t)ldr * GK + kc + cbase + j * 4);
            }
        }
        const uint32_t* Au = As[it & 1];
        const uint32_t* Bu = Bs[it & 1];
#pragma unroll
        for (int ks = 0; ks < 2; ks++) {
            int c2 = ks * 8 + lk;
            uint32_t af[4][4], bf[4][2];
#pragma unroll
            for (int mt = 0; mt < 4; mt++) {
                int r = wr * 64 + mt * 16 + lg;
                af[mt][0] = Au[r * ROWP32 + c2];
                af[mt][1] = Au[(r + 8) * ROWP32 + c2];
                af[mt][2] = Au[r * ROWP32 + c2 + 4];
                af[mt][3] = Au[(r + 8) * ROWP32 + c2 + 4];
            }
#pragma unroll
            for (int nt = 0; nt < 4; nt++) {
                int n = wc * 32 + nt * 8 + lg;
                bf[nt][0] = Bu[n * ROWP32 + c2];
                bf[nt][1] = Bu[n * ROWP32 + c2 + 4];
            }
#pragma unroll
            for (int mt = 0; mt < 4; mt++)
#pragma unroll
                for (int nt = 0; nt < 4; nt++)
                    mma_bf16(acc[mt][nt], af[mt], bf[nt]);
        }
        if (it + 1 < KCHUNKS) {
            int st = (it + 1) & 1;
            uint4 ua0 = make_uint4(pack_bf16(ra[0].x, ra[0].y), pack_bf16(ra[0].z, ra[0].w),
                                   pack_bf16(ra[1].x, ra[1].y), pack_bf16(ra[1].z, ra[1].w));
            uint4 ua1 = make_uint4(pack_bf16(ra[2].x, ra[2].y), pack_bf16(ra[2].z, ra[2].w),
                                   pack_bf16(ra[3].x, ra[3].y), pack_bf16(ra[3].z, ra[3].w));
            uint4 ub0 = make_uint4(pack_bf16(rb[0].x, rb[0].y), pack_bf16(rb[0].z, rb[0].w),
                                   pack_bf16(rb[1].x, rb[1].y), pack_bf16(rb[1].z, rb[1].w));
            uint4 ub1 = make_uint4(pack_bf16(rb[2].x, rb[2].y), pack_bf16(rb[2].z, rb[2].w),
                                   pack_bf16(rb[3].x, rb[3].y), pack_bf16(rb[3].z, rb[3].w));
            *(uint4*)(&As[st][ldr * ROWP32 + c2base])     = ua0;
            *(uint4*)(&As[st][ldr * ROWP32 + c2base + 4]) = ua1;
            *(uint4*)(&Bs[st][ldr * ROWP32 + c2base])     = ub0;
            *(uint4*)(&Bs[st][ldr * ROWP32 + c2base + 4]) = ub1;
            __syncthreads();
        }
    }

    // epilogue: direct stores, float2 per (mt,nt) row pair
#pragma unroll
    for (int mt = 0; mt < 4; mt++) {
        size_t r0 = (size_t)(bm + wr * 64 + mt * 16 + lg);
#pragma unroll
        for (int nt = 0; nt < 4; nt++) {
            int c0 = bn + wc * 32 + nt * 8 + lk * 2;
            float bx = bias[c0], by = bias[c0 + 1];
            float2 v0 = make_float2(acc[mt][nt][0] + bx, acc[mt][nt][1] + by);
            float2 v1 = make_float2(acc[mt][nt][2] + bx, acc[mt][nt][3] + by);
            *(float2*)(C + r0 * N + c0) = v0;
            *(float2*)(C + (r0 + 8) * N + c0) = v1;
        }
    }
}

// ---------------- generic small-seq attention ----------------
__global__ __launch_bounds__(256) void attn_kernel(
    const float* __restrict__ qkv, float* __restrict__ out, int S, int temporal)
{
    extern __shared__ float sm[];
    int h = blockIdx.y;
    int seq = blockIdx.x;
    int base, stride;
    if (temporal) {
        int b = seq / Pp, p = seq % Pp;
        base = b * Ff * Pp + p;
        stride = Pp;
    } else {
        base = seq * Pp;
        stride = 1;
    }

    float* Ks = sm;                 // S * 65
    float* Vs = Ks + S * 65;        // S * 64
    float* qs = Vs + S * 64;        // 64
    float* sc = qs + 64;            // S
    float* red = sc + S;            // 2

    int tid = threadIdx.x;

    for (int idx = tid; idx < S * 64; idx += 256) {
        int s = idx >> 6, d = idx & 63;
        size_t row = (size_t)(base + s * stride) * QKVW;
        Ks[s * 65 + d] = qkv[row + Dd + h * HD + d];
        Vs[s * 64 + d] = qkv[row + 2 * Dd + h * HD + d];
    }
    __syncthreads();

    for (int q = 0; q < S; q++) {
        size_t qrow = (size_t)(base + q * stride);
        if (tid < 64) qs[tid] = qkv[qrow * QKVW + h * HD + tid];
        __syncthreads();

        if (tid < S) {
            const float* kr = Ks + tid * 65;
            float acc = 0.f;
#pragma unroll 16
            for (int d = 0; d < 64; d++) acc += qs[d] * kr[d];
            sc[tid] = acc * 0.125f;
        }
        __syncthreads();

        if (tid < 32) {
            float m = -1e30f;
            for (int j = tid; j < S; j += 32) m = fmaxf(m, sc[j]);
#pragma unroll
            for (int o = 16; o; o >>= 1) m = fmaxf(m, __shfl_xor_sync(0xffffffffu, m, o));
            red[0] = m;
        }
        __syncthreads();
        float smax = red[0];
        if (tid < S) sc[tid] = __expf(sc[tid] - smax);
        __syncthreads();
        if (tid < 32) {
            float s = 0.f;
            for (int j = tid; j < S; j += 32) s += sc[j];
#pragma unroll
            for (int o = 16; o; o >>= 1) s += __shfl_xor_sync(0xffffffffu, s, o);
            red[1] = 1.0f / s;
        }
        __syncthreads();
        float inv = red[1];

        if (tid < 64) {
            float acc = 0.f;
            for (int j = 0; j < S; j++) acc += sc[j] * Vs[j * 64 + tid];
            out[qrow * Dd + h * HD + tid] = acc * inv;
        }
        __syncthreads();
    }
}

// ---------------- fused residual + LayerNorm ----------------
__global__ __launch_bounds__(256) void add_ln_kernel(
    const float* __restrict__ x, const float* __restrict__ y,
    const float* __restrict__ g, const float* __restrict__ b,
    float* __restrict__ out)
{
    __shared__ float row_sm[Dd];
    __shared__ float ps[8], ps2[8];
    __shared__ float red[2];

    size_t row = blockIdx.x;
    const float* xr = x + row * Dd;
    const float* yr = y + row * Dd;
    int tid = threadIdx.x;
    int lane = tid & 31, wid = tid >> 5;

    float s = 0.f, s2 = 0.f;
    for (int d = tid; d < Dd; d += 256) {
        float v = xr[d] + yr[d];
        row_sm[d] = v;
        s += v;
        s2 += v * v;
    }
#pragma unroll
    for (int o = 16; o; o >>= 1) {
        s  += __shfl_xor_sync(0xffffffffu, s, o);
        s2 += __shfl_xor_sync(0xffffffffu, s2, o);
    }
    if (lane == 0) { ps[wid] = s; ps2[wid] = s2; }
    __syncthreads();
    if (tid < 8) {
        s = ps[tid]; s2 = ps2[tid];
#pragma unroll
        for (int o = 4; o; o >>= 1) {
            s  += __shfl_xor_sync(0xffu, s, o);
            s2 += __shfl_xor_sync(0xffu, s2, o);
        }
        if (tid == 0) {
            float mean = s / Dd;
            float var = s2 / Dd - mean * mean;
            red[0] = mean;
            red[1] = rsqrtf(var + 1e-5f);
        }
    }
    __syncthreads();
    float mean = red[0], rstd = red[1];
    for (int d = tid; d < Dd; d += 256)
        out[row * Dd + d] = (row_sm[d] - mean) * rstd * g[d] + b[d];
}

// ---------------- launch ----------------
extern "C" void kernel_launch(void* const* d_in, const int* in_sizes, int n_in,
                              void* d_out, int out_size)
{
    const float* x      = (const float*)d_in[0];
    const float* Wqkv_t = (const float*)d_in[1];
    const float* bqkv_t = (const float*)d_in[2];
    const float* Wo_t   = (const float*)d_in[3];
    const float* bo_t   = (const float*)d_in[4];
    const float* Wqkv_s = (const float*)d_in[5];
    const float* bqkv_s = (const float*)d_in[6];
    const float* Wo_s   = (const float*)d_in[7];
    const float* bo_s   = (const float*)d_in[8];
    const float* g1     = (const float*)d_in[9];
    const float* b1     = (const float*)d_in[10];
    const float* g2     = (const float*)d_in[11];
    const float* b2     = (const float*)d_in[12];
    float* out = (float*)d_out;

    float *qkv, *attn, *y, *x1, *wt;
    cudaGetSymbolAddress((void**)&qkv,  g_qkv);
    cudaGetSymbolAddress((void**)&attn, g_attn);
    cudaGetSymbolAddress((void**)&y,    g_y);
    cudaGetSymbolAddress((void**)&x1,   g_x1);
    cudaGetSymbolAddress((void**)&wt,   g_wt);

    int smem_spatial  = (Pp * 65 + Pp * 64 + 64 + Pp + 2) * (int)sizeof(float);
    int smem_temporal = (Ff * 65 + Ff * 64 + 64 + Ff + 2) * (int)sizeof(float);
    cudaFuncSetAttribute(attn_kernel, cudaFuncAttributeMaxDynamicSharedMemorySize, smem_spatial);

    dim3 tb(32, 8);
    dim3 tg_qkv(QKVW / 32, GK / 32);      // (72, 24)
    dim3 tg_out(Dd / 32, GK / 32);        // (24, 24)
    dim3 gg_qkv(QKVW / 128, NTOK / 128);  // (18, 196)
    dim3 gg_out(Dd / 128, NTOK / 128);    // (6, 196)

    // temporal QKV projection
    transpose32<<<tg_qkv, tb>>>(Wqkv_t, wt, GK, QKVW);
    gemm_mma<<<gg_qkv, 256>>>(x, wt, bqkv_t, qkv, QKVW);
    // temporal attention (S=16)
    attn_kernel<<<dim3(Bb * Pp, Hh), 256, smem_temporal>>>(qkv, attn, Ff, 1);
    // temporal out-projection
    transpose32<<<tg_out, tb>>>(Wo_t, wt, GK, Dd);
    gemm_mma<<<gg_out, 256>>>(attn, wt, bo_t, y, Dd);
    // x1 = LN(x + y)
    add_ln_kernel<<<NTOK, 256>>>(x, y, g1, b1, x1);
    // spatial QKV projection
    transpose32<<<tg_qkv, tb>>>(Wqkv_s, wt, GK, QKVW);
    gemm_mma<<<gg_qkv, 256>>>(x1, wt, bqkv_s, qkv, QKVW);
    // spatial attention (S=196)
    attn_kernel<<<dim3(Bb * Ff, Hh), 256, smem_spatial>>>(qkv, attn, Pp, 0);
    // spatial out-projection
    transpose32<<<tg_out, tb>>>(Wo_s, wt, GK, Dd);
    gemm_mma<<<gg_out, 256>>>(attn, wt, bo_s, y, Dd);
    // out = LN(x1 + y)
    add_ln_kernel<<<NTOK, 256>>>(x1, y, g2, b2, out);
}